// round 16
// baseline (speedup 1.0000x reference)
#include <cuda_runtime.h>
#include <cuda_fp16.h>
#include <cstdint>

#define NT 256
#define LN_EPS 1e-5f
#define MAX_NODES 100000

// smem byte offsets
#define SB_W1  0          // frag-major W1: 4 s x 32 lanes x 80 B = 10240
#define SB_WB  10240      // frag-major Wbig: 12 s x 32 lanes x 80 B = 30720
#define SB_BI  40960      // float b_init [64]
#define SB_BMX 41216      // float folded bias [65]+pad (272 B)
#define SB_EH  41488      // per-warp e-spill: 8 warps x 4096 B
#define SMEM_BYTES 74256

__device__ int    g_edges_is_i64;
__device__ __half g_w1[4 * 32 * 40];
__device__ __half g_wb[12 * 32 * 40];
__device__ float  g_bi[64];
__device__ float  g_bmx[68];
__device__ __half g_nodeh[MAX_NODES * 64];   // fp16 node cache, K-permuted rows

__device__ __host__ __forceinline__ int sigp(int c) {
    return 16 * (c >> 4) + 4 * ((c & 7) >> 1) + 2 * ((c >> 3) & 1) + (c & 1);
}

__global__ void prep_all(const float* __restrict__ node_fts, int n4,
                         const float* __restrict__ W_init,
                         const float* __restrict__ b_init,
                         const float* __restrict__ W_mlp,
                         const float* __restrict__ b_mlp,
                         const float* __restrict__ W_alpha,
                         const float* __restrict__ b_alpha,
                         const long long* __restrict__ e64)
{
    int i = blockIdx.x * blockDim.x + threadIdx.x;
    if (i == 0) {
        int ok = 1;
        for (int j = 0; j < 64; ++j) {
            long long v = e64[j];
            if (v < 0 || v >= (1LL << 31)) ok = 0;
        }
        g_edges_is_i64 = ok;
    }
    if (i < n4) {
        int row = i >> 4, i4 = i & 15;
        float4 v = __ldg((const float4*)node_fts + i);
        __half2 h0 = __floats2half2_rn(v.x, v.y);
        __half2 h1 = __floats2half2_rn(v.z, v.w);
        uint2 u = { *(uint32_t*)&h0, *(uint32_t*)&h1 };
        int off = (i4 >> 3) * 32 + (i4 & 3) * 8 + ((i4 >> 2) & 1) * 4;
        *(uint2*)(g_nodeh + row * 64 + off) = u;
        return;
    }
    int j = i - n4;
    if (j < 64 * 64) {
        int c = j >> 6, k = j & 63;
        int nt = c >> 3, gq = c & 7;
        int s = k >> 4, t4 = (k & 15) >> 2, r = k & 3;
        int lane = gq * 4 + t4;
        g_w1[(s * 32 + lane) * 40 + nt * 4 + r] = __float2half_rn(W_init[sigp(c) * 64 + k]);
    } else if (j < 64 * 64 + 72 * 192) {
        int j2 = j - 64 * 64;
        int c = j2 / 192, k = j2 - c * 192;
        float v = 0.f;
        if (c < 64) {
            int a = sigp(c);
            if (k < 64) {
                float s = 0.f;
                #pragma unroll 8
                for (int m = 0; m < 64; ++m) s += W_mlp[a * 192 + m] * W_init[m * 64 + k];
                v = s;
            } else v = W_mlp[a * 192 + k];
        } else if (c == 64) {
            if (k < 64) {
                float s = 0.f;
                #pragma unroll 8
                for (int m = 0; m < 64; ++m) s += W_alpha[m] * W_init[m * 64 + k];
                v = s;
            } else v = W_alpha[k];
        }
        int nt = c >> 3, gq = c & 7;
        int s = k >> 4, t4 = (k & 15) >> 2, r = k & 3;
        int lane = gq * 4 + t4;
        g_wb[(s * 32 + lane) * 40 + nt * 4 + r] = __float2half_rn(v);
    } else if (j < 64 * 64 + 72 * 192 + 64) {
        int t = j - (64 * 64 + 72 * 192);
        g_bi[t] = b_init[t];
    } else if (j < 64 * 64 + 72 * 192 + 64 + 65) {
        int t = j - (64 * 64 + 72 * 192 + 64);
        float s = (t < 64) ? b_mlp[t] : b_alpha[0];
        const float* wr = (t < 64) ? (W_mlp + t * 192) : W_alpha;
        #pragma unroll 8
        for (int m = 0; m < 64; ++m) s += b_init[m] * wr[m];
        g_bmx[t] = s;
    }
}

__device__ __forceinline__ uint32_t H2(float a, float b) {
    __half2 h = __floats2half2_rn(a, b);
    return *(uint32_t*)&h;
}
__device__ __forceinline__ float tanhap(float x) {
    float r; asm("tanh.approx.f32 %0, %1;" : "=f"(r) : "f"(x));
    return r;
}
__device__ __forceinline__ void mma_f16(float c[4], uint32_t a0, uint32_t a1, uint32_t a2,
                                        uint32_t a3, uint32_t b0, uint32_t b1) {
    asm volatile(
        "mma.sync.aligned.m16n8k16.row.col.f32.f16.f16.f32 "
        "{%0,%1,%2,%3}, {%4,%5,%6,%7}, {%8,%9}, {%0,%1,%2,%3};\n"
        : "+f"(c[0]), "+f"(c[1]), "+f"(c[2]), "+f"(c[3])
        : "r"(a0), "r"(a1), "r"(a2), "r"(a3), "r"(b0), "r"(b1));
}

__global__ void __launch_bounds__(NT, 2)
edge_update_v16(const float* __restrict__ edge_fts,
                const void* __restrict__ edges_raw,
                float* __restrict__ out,
                int n_edges)
{
    extern __shared__ char smc[];
    const int tid = threadIdx.x;
    {
        int4* d1 = (int4*)smc;
        const int4* s1 = (const int4*)g_w1;
        for (int i = tid; i < 10240 / 16; i += NT) d1[i] = s1[i];
        int4* d2 = (int4*)(smc + SB_WB);
        const int4* s2 = (const int4*)g_wb;
        for (int i = tid; i < 30720 / 16; i += NT) d2[i] = s2[i];
        float* bf = (float*)(smc + SB_BI);
        if (tid < 64) bf[tid] = g_bi[tid];
        float* bm = (float*)(smc + SB_BMX);
        if (tid < 65) bm[tid] = g_bmx[tid];
    }
    __syncthreads();

    const __half* sw1 = (const __half*)(smc + SB_W1);
    const __half* swb = (const __half*)(smc + SB_WB);
    const float*  sbi = (const float*)(smc + SB_BI);
    const float*  sbm = (const float*)(smc + SB_BMX);

    const int wid  = tid >> 5;
    const int lane = tid & 31;
    const int gq   = lane >> 2;
    const int t4   = lane & 3;
    const int is64 = g_edges_is_i64;
    const long long* e64 = (const long long*)edges_raw;
    const int*       e32 = (const int*)edges_raw;
    const float bma = sbm[64];
    char* ebase = smc + SB_EH + wid * 4096;

    const char* eB = (const char*)edge_fts;
    const char* nH = (const char*)g_nodeh;
    const int ntiles  = (n_edges + 31) >> 5;
    const int wstride = gridDim.x * 8;

#define LOADIDX(dh, dt, tw) do { \
        size_t ep = (size_t)min(((tw) << 5) + lane, n_edges - 1); \
        if (is64) { dh = (int)e64[ep]; dt = (int)e64[ep + (size_t)n_edges]; } \
        else      { dh = e32[ep];      dt = e32[ep + (size_t)n_edges]; } \
    } while (0)

#define SETOFFS(HI, TI, tw) do { \
        _Pragma("unroll") \
        for (int c = 0; c < 4; ++c) { \
            const int row = c * 8 + gq; \
            const int er  = min(((tw) << 5) + row, n_edges - 1); \
            oE[c] = (uint32_t)er * 256u + (uint32_t)(t4 * 16); \
            const int hi = __shfl_sync(0xffffffffu, HI, row); \
            const int ti = __shfl_sync(0xffffffffu, TI, row); \
            oH[c] = (uint32_t)hi * 128u + (uint32_t)(t4 * 16); \
            oT[c] = (uint32_t)ti * 128u + (uint32_t)(t4 * 16); \
        } \
    } while (0)

// 18 mma on both 16-row halves sharing one weight-fragment load
#define WB_MMA2(sidx, A0, A1, A2, A3, B0, B1, B2, B3) do { \
        const __half* wp = swb + ((sidx) * 32 + lane) * 40; \
        uint4 wA = *(const uint4*)wp; \
        uint4 wBv = *(const uint4*)(wp + 8); \
        uint4 wC = *(const uint4*)(wp + 16); \
        uint4 wD = *(const uint4*)(wp + 24); \
        uint2 wE = *(const uint2*)(wp + 32); \
        mma_f16(accB[0][0], A0, A1, A2, A3, wA.x, wA.y); \
        mma_f16(accB[1][0], B0, B1, B2, B3, wA.x, wA.y); \
        mma_f16(accB[0][1], A0, A1, A2, A3, wA.z, wA.w); \
        mma_f16(accB[1][1], B0, B1, B2, B3, wA.z, wA.w); \
        mma_f16(accB[0][2], A0, A1, A2, A3, wBv.x, wBv.y); \
        mma_f16(accB[1][2], B0, B1, B2, B3, wBv.x, wBv.y); \
        mma_f16(accB[0][3], A0, A1, A2, A3, wBv.z, wBv.w); \
        mma_f16(accB[1][3], B0, B1, B2, B3, wBv.z, wBv.w); \
        mma_f16(accB[0][4], A0, A1, A2, A3, wC.x, wC.y); \
        mma_f16(accB[1][4], B0, B1, B2, B3, wC.x, wC.y); \
        mma_f16(accB[0][5], A0, A1, A2, A3, wC.z, wC.w); \
        mma_f16(accB[1][5], B0, B1, B2, B3, wC.z, wC.w); \
        mma_f16(accB[0][6], A0, A1, A2, A3, wD.x, wD.y); \
        mma_f16(accB[1][6], B0, B1, B2, B3, wD.x, wD.y); \
        mma_f16(accB[0][7], A0, A1, A2, A3, wD.z, wD.w); \
        mma_f16(accB[1][7], B0, B1, B2, B3, wD.z, wD.w); \
        mma_f16(accB[0][8], A0, A1, A2, A3, wE.x, wE.y); \
        mma_f16(accB[1][8], B0, B1, B2, B3, wE.x, wE.y); \
    } while (0)

#define W1_MMA2(sidx, A0, A1, A2, A3, B0, B1, B2, B3) do { \
        const __half* wp = sw1 + ((sidx) * 32 + lane) * 40; \
        uint4 wA = *(const uint4*)wp; \
        uint4 wBv = *(const uint4*)(wp + 8); \
        uint4 wC = *(const uint4*)(wp + 16); \
        uint4 wD = *(const uint4*)(wp + 24); \
        mma_f16(accE[0][0], A0, A1, A2, A3, wA.x, wA.y); \
        mma_f16(accE[1][0], B0, B1, B2, B3, wA.x, wA.y); \
        mma_f16(accE[0][1], A0, A1, A2, A3, wA.z, wA.w); \
        mma_f16(accE[1][1], B0, B1, B2, B3, wA.z, wA.w); \
        mma_f16(accE[0][2], A0, A1, A2, A3, wBv.x, wBv.y); \
        mma_f16(accE[1][2], B0, B1, B2, B3, wBv.x, wBv.y); \
        mma_f16(accE[0][3], A0, A1, A2, A3, wBv.z, wBv.w); \
        mma_f16(accE[1][3], B0, B1, B2, B3, wBv.z, wBv.w); \
        mma_f16(accE[0][4], A0, A1, A2, A3, wC.x, wC.y); \
        mma_f16(accE[1][4], B0, B1, B2, B3, wC.x, wC.y); \
        mma_f16(accE[0][5], A0, A1, A2, A3, wC.z, wC.w); \
        mma_f16(accE[1][5], B0, B1, B2, B3, wC.z, wC.w); \
        mma_f16(accE[0][6], A0, A1, A2, A3, wD.x, wD.y); \
        mma_f16(accE[1][6], B0, B1, B2, B3, wD.x, wD.y); \
        mma_f16(accE[0][7], A0, A1, A2, A3, wD.z, wD.w); \
        mma_f16(accE[1][7], B0, B1, B2, B3, wD.z, wD.w); \
    } while (0)

#define CVT8(V0, V1, V2, V3, L0, L1, H0, H1, L2, L3, H2v, H3v) \
        const uint32_t L0 = H2(V0.x, V0.y), L1 = H2(V1.x, V1.y); \
        const uint32_t H0 = H2(V0.z, V0.w), H1 = H2(V1.z, V1.w); \
        const uint32_t L2 = H2(V2.x, V2.y), L3 = H2(V3.x, V3.y); \
        const uint32_t H2v = H2(V2.z, V2.w), H3v = H2(V3.z, V3.w)

    int wt = blockIdx.x * 8 + wid;
    if (wt >= ntiles) return;

    // ---------------- prologue ----------------
    int hidx, tidx;
    uint32_t oE[4], oH[4], oT[4];
    LOADIDX(hidx, tidx, wt);
    SETOFFS(hidx, tidx, wt);
    float4 vc0 = __ldg((const float4*)(eB + oE[0]));
    float4 vc1 = __ldg((const float4*)(eB + oE[1]));
    float4 vc2 = __ldg((const float4*)(eB + oE[2]));
    float4 vc3 = __ldg((const float4*)(eB + oE[3]));

    for (; wt < ntiles; wt += wstride) {
        const int tb  = wt << 5;
        const int rem = min(32, n_edges - tb);
        const int wtn = min(wt + wstride, ntiles - 1);
        int hidxN, tidxN;
        LOADIDX(hidxN, tidxN, wtn);

        // ================ Phase A: e-GEMM (32 rows) ================
        float accE[2][8][4];
        #pragma unroll
        for (int h = 0; h < 2; ++h)
            #pragma unroll
            for (int b = 0; b < 8; ++b)
                #pragma unroll
                for (int c = 0; c < 4; ++c) accE[h][b][c] = 0.f;

        uint32_t s2f[8], s3f[8];
        {
            // s0 (carried vc), issue s1
            float4 u0 = __ldg((const float4*)(eB + oE[0] + 64));
            float4 u1 = __ldg((const float4*)(eB + oE[1] + 64));
            float4 u2 = __ldg((const float4*)(eB + oE[2] + 64));
            float4 u3 = __ldg((const float4*)(eB + oE[3] + 64));
            { CVT8(vc0, vc1, vc2, vc3, a0, a1, b0, b1, a2, a3, b2, b3);
              W1_MMA2(0, a0, a1, b0, b1, a2, a3, b2, b3); }
            // issue s2
            float4 x0 = __ldg((const float4*)(eB + oE[0] + 128));
            float4 x1 = __ldg((const float4*)(eB + oE[1] + 128));
            float4 x2 = __ldg((const float4*)(eB + oE[2] + 128));
            float4 x3 = __ldg((const float4*)(eB + oE[3] + 128));
            { CVT8(u0, u1, u2, u3, a0, a1, b0, b1, a2, a3, b2, b3);
              W1_MMA2(1, a0, a1, b0, b1, a2, a3, b2, b3); }
            // issue s3
            float4 z0 = __ldg((const float4*)(eB + oE[0] + 192));
            float4 z1 = __ldg((const float4*)(eB + oE[1] + 192));
            float4 z2 = __ldg((const float4*)(eB + oE[2] + 192));
            float4 z3 = __ldg((const float4*)(eB + oE[3] + 192));
            s2f[0] = H2(x0.x, x0.y); s2f[1] = H2(x1.x, x1.y);
            s2f[2] = H2(x0.z, x0.w); s2f[3] = H2(x1.z, x1.w);
            s2f[4] = H2(x2.x, x2.y); s2f[5] = H2(x3.x, x3.y);
            s2f[6] = H2(x2.z, x2.w); s2f[7] = H2(x3.z, x3.w);
            W1_MMA2(2, s2f[0], s2f[1], s2f[2], s2f[3], s2f[4], s2f[5], s2f[6], s2f[7]);
            s3f[0] = H2(z0.x, z0.y); s3f[1] = H2(z1.x, z1.y);
            s3f[2] = H2(z0.z, z0.w); s3f[3] = H2(z1.z, z1.w);
            s3f[4] = H2(z2.x, z2.y); s3f[5] = H2(z3.x, z3.y);
            s3f[6] = H2(z2.z, z2.w); s3f[7] = H2(z3.z, z3.w);
            W1_MMA2(3, s3f[0], s3f[1], s3f[2], s3f[3], s3f[4], s3f[5], s3f[6], s3f[7]);
        }

        // node pair-0 loads (consumed after phase-B edge steps — latency covered)
        uint4 cc0 = __ldg((const uint4*)(nH + oH[0]));
        uint4 cc1 = __ldg((const uint4*)(nH + oH[1]));
        uint4 cc2 = __ldg((const uint4*)(nH + oH[2]));
        uint4 cc3 = __ldg((const uint4*)(nH + oH[3]));

        // pack e (+b_init) to fp16 and spill to smem (same-thread, no sync)
        #pragma unroll
        for (int mt = 0; mt < 2; ++mt)
            #pragma unroll
            for (int hf = 0; hf < 2; ++hf) {
                const int h2 = hf * 2;
                #pragma unroll
                for (int j = 0; j < 2; ++j) {
                    const int J = 2 * j, J2 = 2 * j + 1;
                    float4 biA = *(const float4*)&sbi[J * 16 + t4 * 4];
                    float4 biB = *(const float4*)&sbi[J2 * 16 + t4 * 4];
                    uint4 U;
                    U.x = H2(accE[mt][2 * J][h2] + biA.x,      accE[mt][2 * J][h2 + 1] + biA.y);
                    U.y = H2(accE[mt][2 * J + 1][h2] + biA.z,  accE[mt][2 * J + 1][h2 + 1] + biA.w);
                    U.z = H2(accE[mt][2 * J2][h2] + biB.x,     accE[mt][2 * J2][h2 + 1] + biB.y);
                    U.w = H2(accE[mt][2 * J2 + 1][h2] + biB.z, accE[mt][2 * J2 + 1][h2 + 1] + biB.w);
                    *(uint4*)(ebase + ((mt * 4 + hf * 2 + j) * 512) + lane * 16) = U;
                }
            }

        // ================ Phase B: big-GEMM (32 rows) ================
        float accB[2][9][4];
        #pragma unroll
        for (int h = 0; h < 2; ++h)
            #pragma unroll
            for (int b = 0; b < 9; ++b)
                #pragma unroll
                for (int c = 0; c < 4; ++c) accB[h][b][c] = 0.f;

        {
            // s0/s1 edge re-read (L1/L2 hot)
            float4 r0 = __ldg((const float4*)(eB + oE[0]));
            float4 r1 = __ldg((const float4*)(eB + oE[1]));
            float4 r2 = __ldg((const float4*)(eB + oE[2]));
            float4 r3 = __ldg((const float4*)(eB + oE[3]));
            float4 u0 = __ldg((const float4*)(eB + oE[0] + 64));
            float4 u1 = __ldg((const float4*)(eB + oE[1] + 64));
            float4 u2 = __ldg((const float4*)(eB + oE[2] + 64));
            float4 u3 = __ldg((const float4*)(eB + oE[3] + 64));
            { CVT8(r0, r1, r2, r3, a0, a1, b0, b1, a2, a3, b2, b3);
              WB_MMA2(0, a0, a1, b0, b1, a2, a3, b2, b3); }
            { CVT8(u0, u1, u2, u3, a0, a1, b0, b1, a2, a3, b2, b3);
              WB_MMA2(1, a0, a1, b0, b1, a2, a3, b2, b3); }
            WB_MMA2(2, s2f[0], s2f[1], s2f[2], s2f[3], s2f[4], s2f[5], s2f[6], s2f[7]);
            WB_MMA2(3, s3f[0], s3f[1], s3f[2], s3f[3], s3f[4], s3f[5], s3f[6], s3f[7]);
        }

        // node phase: pairs 0..3 (head j0 = cc, head j1, tail j0, tail j1)
        #pragma unroll
        for (int pj = 0; pj < 4; ++pj) {
            uint4 nn0, nn1, nn2, nn3;
            if (pj < 3) {
                const int np = pj + 1;
                const uint32_t* ob = (np >> 1) ? oT : oH;
                const uint32_t ofs = (uint32_t)((np & 1) * 64);
                nn0 = __ldg((const uint4*)(nH + ob[0] + ofs));
                nn1 = __ldg((const uint4*)(nH + ob[1] + ofs));
                nn2 = __ldg((const uint4*)(nH + ob[2] + ofs));
                nn3 = __ldg((const uint4*)(nH + ob[3] + ofs));
            }
            WB_MMA2(4 + 2 * pj, cc0.x, cc1.x, cc0.y, cc1.y, cc2.x, cc3.x, cc2.y, cc3.y);
            WB_MMA2(5 + 2 * pj, cc0.z, cc1.z, cc0.w, cc1.w, cc2.z, cc3.z, cc2.w, cc3.w);
            if (pj < 3) { cc0 = nn0; cc1 = nn1; cc2 = nn2; cc3 = nn3; }
        }

        // next-tile offsets (oE/oH/oT now dead for this tile)
        SETOFFS(hidxN, tidxN, wtn);

        // ================ Epilogue ================
        #pragma unroll
        for (int mt = 0; mt < 2; ++mt) {
            #pragma unroll
            for (int hf = 0; hf < 2; ++hf) {
                const int h2  = hf * 2;
                const int row = mt * 16 + hf * 8 + gq;

                float p[16], s1 = 0.f, s2 = 0.f;
                #pragma unroll
                for (int J = 0; J < 4; ++J) {
                    float4 bm4 = *(const float4*)&sbm[J * 16 + t4 * 4];
                    float pre[4] = { accB[mt][2 * J][h2]     + bm4.x,
                                     accB[mt][2 * J][h2 + 1] + bm4.y,
                                     accB[mt][2 * J + 1][h2]     + bm4.z,
                                     accB[mt][2 * J + 1][h2 + 1] + bm4.w };
                    #pragma unroll
                    for (int c = 0; c < 4; ++c) {
                        float th = tanhap(pre[c]);
                        p[J * 4 + c] = th;
                        s1 += th; s2 += th * th;
                    }
                }
                s1 += __shfl_xor_sync(0xffffffffu, s1, 1);
                s1 += __shfl_xor_sync(0xffffffffu, s1, 2);
                s2 += __shfl_xor_sync(0xffffffffu, s2, 1);
                s2 += __shfl_xor_sync(0xffffffffu, s2, 2);
                float ap = accB[mt][8][h2] + bma;
                ap = __shfl_sync(0xffffffffu, ap, lane & ~3);
                const float alpha = __fdividef(1.f, 1.f + __expf(-ap));
                const float mean  = s1 * (1.f / 64.f);
                const float var   = s2 * (1.f / 64.f) - mean * mean;
                const float rstd  = rsqrtf(var + LN_EPS) * alpha;

                // e readback from smem spill
                uint4 q0 = *(const uint4*)(ebase + ((mt * 4 + hf * 2) * 512) + lane * 16);
                uint4 q1 = *(const uint4*)(ebase + ((mt * 4 + hf * 2 + 1) * 512) + lane * 16);
                const uint32_t eharr[8] = { q0.x, q0.y, q0.z, q0.w, q1.x, q1.y, q1.z, q1.w };

                float y[16], u1 = 0.f, u2 = 0.f;
                #pragma unroll
                for (int J = 0; J < 4; ++J) {
                    float2 e01 = __half22float2(*(const __half2*)&eharr[J * 2]);
                    float2 e23 = __half22float2(*(const __half2*)&eharr[J * 2 + 1]);
                    float y0 = e01.x + (p[J * 4 + 0] - mean) * rstd;
                    float y1 = e01.y + (p[J * 4 + 1] - mean) * rstd;
                    float y2 = e23.x + (p[J * 4 + 2] - mean) * rstd;
                    float y3 = e23.y + (p[J * 4 + 3] - mean) * rstd;
                    y[J * 4 + 0] = y0; y[J * 4 + 1] = y1; y[J * 4 + 2] = y2; y[J * 4 + 3] = y3;
                    u1 += y0 + y1 + y2 + y3;
                    u2 += y0 * y0 + y1 * y1 + y2 * y2 + y3 * y3;
                }
                u1 += __shfl_xor_sync(0xffffffffu, u1, 1);
                u1 += __shfl_xor_sync(0xffffffffu, u1, 2);
                u2 += __shfl_xor_sync(0xffffffffu, u2, 1);
                u2 += __shfl_xor_sync(0xffffffffu, u2, 2);
                const float m2  = u1 * (1.f / 64.f);
                const float v2  = u2 * (1.f / 64.f) - m2 * m2;
                const float rs2 = rsqrtf(v2 + LN_EPS);

                if (row < rem) {
                    float* op = out + (size_t)(tb + row) * 64;
                    #pragma unroll
                    for (int J = 0; J < 4; ++J) {
                        float4 o;
                        o.x = (y[J * 4 + 0] - m2) * rs2;
                        o.y = (y[J * 4 + 1] - m2) * rs2;
                        o.z = (y[J * 4 + 2] - m2) * rs2;
                        o.w = (y[J * 4 + 3] - m2) * rs2;
                        __stcs((float4*)(op + J * 16 + t4 * 4), o);
                    }
                }
            }
            if (mt == 0) {
                // prefetch next tile's edge s0 across the second half-epilogue
                vc0 = __ldg((const float4*)(eB + oE[0]));
                vc1 = __ldg((const float4*)(eB + oE[1]));
                vc2 = __ldg((const float4*)(eB + oE[2]));
                vc3 = __ldg((const float4*)(eB + oE[3]));
            }
        }
    }
#undef LOADIDX
#undef SETOFFS
#undef WB_MMA2
#undef W1_MMA2
#undef CVT8
}

extern "C" void kernel_launch(void* const* d_in, const int* in_sizes, int n_in,
                              void* d_out, int out_size)
{
    const float* node_fts = (const float*)d_in[0];
    const float* edge_fts = (const float*)d_in[1];
    const void*  edges    = d_in[2];
    const float* W_init   = (const float*)d_in[3];
    const float* b_init   = (const float*)d_in[4];
    const float* W_mlp    = (const float*)d_in[5];
    const float* b_mlp    = (const float*)d_in[6];
    const float* W_alpha  = (const float*)d_in[7];
    const float* b_alpha  = (const float*)d_in[8];
    float*       out      = (float*)d_out;

    const int n_edges = in_sizes[1] / 64;
    const int n4      = in_sizes[0] / 4;
    const int ntiles  = (n_edges + 31) / 32;

    int nsm = 148;
    cudaDeviceGetAttribute(&nsm, cudaDevAttrMultiProcessorCount, 0);
    int need = (ntiles + 7) / 8;
    int maxg = 2 * nsm;
    int grid = need < maxg ? need : maxg;

    const int prep_threads = n4 + 64 * 64 + 72 * 192 + 64 + 65;

    cudaFuncSetAttribute(edge_update_v16,
                         cudaFuncAttributeMaxDynamicSharedMemorySize, SMEM_BYTES);
    prep_all<<<(prep_threads + 255) / 256, 256>>>(node_fts, n4, W_init, b_init,
                                                  W_mlp, b_mlp, W_alpha, b_alpha,
                                                  (const long long*)edges);
    edge_update_v16<<<grid, NT, SMEM_BYTES>>>(edge_fts, edges, out, n_edges);
}

// round 17
// speedup vs baseline: 1.0429x; 1.0429x over previous
#include <cuda_runtime.h>
#include <cuda_fp16.h>
#include <cstdint>

#define NT 384
#define LN_EPS 1e-5f
#define MAX_NODES 100000

// smem byte offsets
#define SB_W1  0          // frag-major W1: 4 s x 32 lanes x 80 B = 10240
#define SB_WB  10240      // frag-major Wbig: 12 s x 32 lanes x 80 B = 30720
#define SB_BI  40960      // float b_init [64]
#define SB_BMX 41216      // float folded bias [65]+pad
#define SMEM_BYTES 41488

__device__ int    g_edges_is_i64;
__device__ __half g_w1[4 * 32 * 40];
__device__ __half g_wb[12 * 32 * 40];
__device__ float  g_bi[64];
__device__ float  g_bmx[68];
__device__ __half g_nodeh[MAX_NODES * 64];   // fp16 node cache, K-permuted rows

__device__ __host__ __forceinline__ int sigp(int c) {
    return 16 * (c >> 4) + 4 * ((c & 7) >> 1) + 2 * ((c >> 3) & 1) + (c & 1);
}

__global__ void prep_all(const float* __restrict__ node_fts, int n4,
                         const float* __restrict__ W_init,
                         const float* __restrict__ b_init,
                         const float* __restrict__ W_mlp,
                         const float* __restrict__ b_mlp,
                         const float* __restrict__ W_alpha,
                         const float* __restrict__ b_alpha,
                         const long long* __restrict__ e64)
{
    int i = blockIdx.x * blockDim.x + threadIdx.x;
    if (i == 0) {
        int ok = 1;
        for (int j = 0; j < 64; ++j) {
            long long v = e64[j];
            if (v < 0 || v >= (1LL << 31)) ok = 0;
        }
        g_edges_is_i64 = ok;
    }
    if (i < n4) {
        int row = i >> 4, i4 = i & 15;
        float4 v = __ldg((const float4*)node_fts + i);
        __half2 h0 = __floats2half2_rn(v.x, v.y);
        __half2 h1 = __floats2half2_rn(v.z, v.w);
        uint2 u = { *(uint32_t*)&h0, *(uint32_t*)&h1 };
        int off = (i4 >> 3) * 32 + (i4 & 3) * 8 + ((i4 >> 2) & 1) * 4;
        *(uint2*)(g_nodeh + row * 64 + off) = u;
        return;
    }
    int j = i - n4;
    if (j < 64 * 64) {
        int c = j >> 6, k = j & 63;
        int nt = c >> 3, gq = c & 7;
        int s = k >> 4, t4 = (k & 15) >> 2, r = k & 3;
        int lane = gq * 4 + t4;
        g_w1[(s * 32 + lane) * 40 + nt * 4 + r] = __float2half_rn(W_init[sigp(c) * 64 + k]);
    } else if (j < 64 * 64 + 72 * 192) {
        int j2 = j - 64 * 64;
        int c = j2 / 192, k = j2 - c * 192;
        float v = 0.f;
        if (c < 64) {
            int a = sigp(c);
            if (k < 64) {
                float s = 0.f;
                #pragma unroll 8
                for (int m = 0; m < 64; ++m) s += W_mlp[a * 192 + m] * W_init[m * 64 + k];
                v = s;
            } else v = W_mlp[a * 192 + k];
        } else if (c == 64) {
            if (k < 64) {
                float s = 0.f;
                #pragma unroll 8
                for (int m = 0; m < 64; ++m) s += W_alpha[m] * W_init[m * 64 + k];
                v = s;
            } else v = W_alpha[k];
        }
        int nt = c >> 3, gq = c & 7;
        int s = k >> 4, t4 = (k & 15) >> 2, r = k & 3;
        int lane = gq * 4 + t4;
        g_wb[(s * 32 + lane) * 40 + nt * 4 + r] = __float2half_rn(v);
    } else if (j < 64 * 64 + 72 * 192 + 64) {
        int t = j - (64 * 64 + 72 * 192);
        g_bi[t] = b_init[t];
    } else if (j < 64 * 64 + 72 * 192 + 64 + 65) {
        int t = j - (64 * 64 + 72 * 192 + 64);
        float s = (t < 64) ? b_mlp[t] : b_alpha[0];
        const float* wr = (t < 64) ? (W_mlp + t * 192) : W_alpha;
        #pragma unroll 8
        for (int m = 0; m < 64; ++m) s += b_init[m] * wr[m];
        g_bmx[t] = s;
    }
}

__device__ __forceinline__ uint32_t H2(float a, float b) {
    __half2 h = __floats2half2_rn(a, b);
    return *(uint32_t*)&h;
}
__device__ __forceinline__ float tanhap(float x) {
    float r; asm("tanh.approx.f32 %0, %1;" : "=f"(r) : "f"(x));
    return r;
}
__device__ __forceinline__ void mma_f16(float c[4], uint32_t a0, uint32_t a1, uint32_t a2,
                                        uint32_t a3, uint32_t b0, uint32_t b1) {
    asm volatile(
        "mma.sync.aligned.m16n8k16.row.col.f32.f16.f16.f32 "
        "{%0,%1,%2,%3}, {%4,%5,%6,%7}, {%8,%9}, {%0,%1,%2,%3};\n"
        : "+f"(c[0]), "+f"(c[1]), "+f"(c[2]), "+f"(c[3])
        : "r"(a0), "r"(a1), "r"(a2), "r"(a3), "r"(b0), "r"(b1));
}

__global__ void __launch_bounds__(NT, 1)
edge_update_v17(const float* __restrict__ edge_fts,
                const void* __restrict__ edges_raw,
                float* __restrict__ out,
                int n_edges)
{
    extern __shared__ char smc[];
    const int tid = threadIdx.x;
    {
        int4* d1 = (int4*)smc;
        const int4* s1 = (const int4*)g_w1;
        for (int i = tid; i < 10240 / 16; i += NT) d1[i] = s1[i];
        int4* d2 = (int4*)(smc + SB_WB);
        const int4* s2 = (const int4*)g_wb;
        for (int i = tid; i < 30720 / 16; i += NT) d2[i] = s2[i];
        float* bf = (float*)(smc + SB_BI);
        if (tid < 64) bf[tid] = g_bi[tid];
        float* bm = (float*)(smc + SB_BMX);
        if (tid < 65) bm[tid] = g_bmx[tid];
    }
    __syncthreads();

    const __half* sw1 = (const __half*)(smc + SB_W1);
    const __half* swb = (const __half*)(smc + SB_WB);
    const float*  sbi = (const float*)(smc + SB_BI);
    const float*  sbm = (const float*)(smc + SB_BMX);

    const int wid  = tid >> 5;
    const int lane = tid & 31;
    const int gq   = lane >> 2;
    const int t4   = lane & 3;
    const int is64 = g_edges_is_i64;
    const long long* e64 = (const long long*)edges_raw;
    const int*       e32 = (const int*)edges_raw;
    const float bma = sbm[64];

    const char* eB = (const char*)edge_fts;
    const char* nH = (const char*)g_nodeh;
    const int ntiles  = (n_edges + 31) >> 5;
    const int wstride = gridDim.x * 12;

#define LOADIDX(dh, dt, tw) do { \
        size_t ep = (size_t)min(((tw) << 5) + lane, n_edges - 1); \
        if (is64) { dh = (int)e64[ep]; dt = (int)e64[ep + (size_t)n_edges]; } \
        else      { dh = e32[ep];      dt = e32[ep + (size_t)n_edges]; } \
    } while (0)

#define SETOFFS(HI, TI, tw) do { \
        _Pragma("unroll") \
        for (int c = 0; c < 4; ++c) { \
            const int row = c * 8 + gq; \
            const int er  = min(((tw) << 5) + row, n_edges - 1); \
            oE[c] = (uint32_t)er * 256u + (uint32_t)(t4 * 16); \
            const int hi = __shfl_sync(0xffffffffu, HI, row); \
            const int ti = __shfl_sync(0xffffffffu, TI, row); \
            oH[c] = (uint32_t)hi * 128u + (uint32_t)(t4 * 16); \
            oT[c] = (uint32_t)ti * 128u + (uint32_t)(t4 * 16); \
        } \
    } while (0)

#define WB_MMA2(sidx, A0, A1, A2, A3, B0, B1, B2, B3) do { \
        const __half* wp = swb + ((sidx) * 32 + lane) * 40; \
        uint4 wA = *(const uint4*)wp; \
        uint4 wBv = *(const uint4*)(wp + 8); \
        uint4 wC = *(const uint4*)(wp + 16); \
        uint4 wD = *(const uint4*)(wp + 24); \
        uint2 wE = *(const uint2*)(wp + 32); \
        mma_f16(accB[0][0], A0, A1, A2, A3, wA.x, wA.y); \
        mma_f16(accB[1][0], B0, B1, B2, B3, wA.x, wA.y); \
        mma_f16(accB[0][1], A0, A1, A2, A3, wA.z, wA.w); \
        mma_f16(accB[1][1], B0, B1, B2, B3, wA.z, wA.w); \
        mma_f16(accB[0][2], A0, A1, A2, A3, wBv.x, wBv.y); \
        mma_f16(accB[1][2], B0, B1, B2, B3, wBv.x, wBv.y); \
        mma_f16(accB[0][3], A0, A1, A2, A3, wBv.z, wBv.w); \
        mma_f16(accB[1][3], B0, B1, B2, B3, wBv.z, wBv.w); \
        mma_f16(accB[0][4], A0, A1, A2, A3, wC.x, wC.y); \
        mma_f16(accB[1][4], B0, B1, B2, B3, wC.x, wC.y); \
        mma_f16(accB[0][5], A0, A1, A2, A3, wC.z, wC.w); \
        mma_f16(accB[1][5], B0, B1, B2, B3, wC.z, wC.w); \
        mma_f16(accB[0][6], A0, A1, A2, A3, wD.x, wD.y); \
        mma_f16(accB[1][6], B0, B1, B2, B3, wD.x, wD.y); \
        mma_f16(accB[0][7], A0, A1, A2, A3, wD.z, wD.w); \
        mma_f16(accB[1][7], B0, B1, B2, B3, wD.z, wD.w); \
        mma_f16(accB[0][8], A0, A1, A2, A3, wE.x, wE.y); \
        mma_f16(accB[1][8], B0, B1, B2, B3, wE.x, wE.y); \
    } while (0)

#define W1_MMA2(sidx, A0, A1, A2, A3, B0, B1, B2, B3) do { \
        const __half* wp = sw1 + ((sidx) * 32 + lane) * 40; \
        uint4 wA = *(const uint4*)wp; \
        uint4 wBv = *(const uint4*)(wp + 8); \
        uint4 wC = *(const uint4*)(wp + 16); \
        uint4 wD = *(const uint4*)(wp + 24); \
        mma_f16(accE[0][0], A0, A1, A2, A3, wA.x, wA.y); \
        mma_f16(accE[1][0], B0, B1, B2, B3, wA.x, wA.y); \
        mma_f16(accE[0][1], A0, A1, A2, A3, wA.z, wA.w); \
        mma_f16(accE[1][1], B0, B1, B2, B3, wA.z, wA.w); \
        mma_f16(accE[0][2], A0, A1, A2, A3, wBv.x, wBv.y); \
        mma_f16(accE[1][2], B0, B1, B2, B3, wBv.x, wBv.y); \
        mma_f16(accE[0][3], A0, A1, A2, A3, wBv.z, wBv.w); \
        mma_f16(accE[1][3], B0, B1, B2, B3, wBv.z, wBv.w); \
        mma_f16(accE[0][4], A0, A1, A2, A3, wC.x, wC.y); \
        mma_f16(accE[1][4], B0, B1, B2, B3, wC.x, wC.y); \
        mma_f16(accE[0][5], A0, A1, A2, A3, wC.z, wC.w); \
        mma_f16(accE[1][5], B0, B1, B2, B3, wC.z, wC.w); \
        mma_f16(accE[0][6], A0, A1, A2, A3, wD.x, wD.y); \
        mma_f16(accE[1][6], B0, B1, B2, B3, wD.x, wD.y); \
        mma_f16(accE[0][7], A0, A1, A2, A3, wD.z, wD.w); \
        mma_f16(accE[1][7], B0, B1, B2, B3, wD.z, wD.w); \
    } while (0)

#define CVT8(V0, V1, V2, V3, L0, L1, H0, H1, L2, L3, H2v, H3v) \
        const uint32_t L0 = H2(V0.x, V0.y), L1 = H2(V1.x, V1.y); \
        const uint32_t H0 = H2(V0.z, V0.w), H1 = H2(V1.z, V1.w); \
        const uint32_t L2 = H2(V2.x, V2.y), L3 = H2(V3.x, V3.y); \
        const uint32_t H2v = H2(V2.z, V2.w), H3v = H2(V3.z, V3.w)

    int wt = blockIdx.x * 12 + wid;
    if (wt >= ntiles) return;

    // ---------------- prologue ----------------
    int hidx, tidx;
    uint32_t oE[4], oH[4], oT[4];
    LOADIDX(hidx, tidx, wt);
    SETOFFS(hidx, tidx, wt);
    float4 vc0 = __ldg((const float4*)(eB + oE[0]));
    float4 vc1 = __ldg((const float4*)(eB + oE[1]));
    float4 vc2 = __ldg((const float4*)(eB + oE[2]));
    float4 vc3 = __ldg((const float4*)(eB + oE[3]));

    for (; wt < ntiles; wt += wstride) {
        const int tb  = wt << 5;
        const int rem = min(32, n_edges - tb);
        const int wtn = min(wt + wstride, ntiles - 1);
        int hidxN, tidxN;
        LOADIDX(hidxN, tidxN, wtn);

        // ================ Phase A: e-GEMM (32 rows) ================
        float accE[2][8][4];
        #pragma unroll
        for (int h = 0; h < 2; ++h)
            #pragma unroll
            for (int b = 0; b < 8; ++b)
                #pragma unroll
                for (int c = 0; c < 4; ++c) accE[h][b][c] = 0.f;

        uint32_t s2f[8], s3f[8];
        {
            float4 u0 = __ldg((const float4*)(eB + oE[0] + 64));
            float4 u1 = __ldg((const float4*)(eB + oE[1] + 64));
            float4 u2 = __ldg((const float4*)(eB + oE[2] + 64));
            float4 u3 = __ldg((const float4*)(eB + oE[3] + 64));
            { CVT8(vc0, vc1, vc2, vc3, a0, a1, b0, b1, a2, a3, b2, b3);
              W1_MMA2(0, a0, a1, b0, b1, a2, a3, b2, b3); }
            float4 x0 = __ldg((const float4*)(eB + oE[0] + 128));
            float4 x1 = __ldg((const float4*)(eB + oE[1] + 128));
            float4 x2 = __ldg((const float4*)(eB + oE[2] + 128));
            float4 x3 = __ldg((const float4*)(eB + oE[3] + 128));
            { CVT8(u0, u1, u2, u3, a0, a1, b0, b1, a2, a3, b2, b3);
              W1_MMA2(1, a0, a1, b0, b1, a2, a3, b2, b3); }
            float4 z0 = __ldg((const float4*)(eB + oE[0] + 192));
            float4 z1 = __ldg((const float4*)(eB + oE[1] + 192));
            float4 z2 = __ldg((const float4*)(eB + oE[2] + 192));
            float4 z3 = __ldg((const float4*)(eB + oE[3] + 192));
            s2f[0] = H2(x0.x, x0.y); s2f[1] = H2(x1.x, x1.y);
            s2f[2] = H2(x0.z, x0.w); s2f[3] = H2(x1.z, x1.w);
            s2f[4] = H2(x2.x, x2.y); s2f[5] = H2(x3.x, x3.y);
            s2f[6] = H2(x2.z, x2.w); s2f[7] = H2(x3.z, x3.w);
            W1_MMA2(2, s2f[0], s2f[1], s2f[2], s2f[3], s2f[4], s2f[5], s2f[6], s2f[7]);
            s3f[0] = H2(z0.x, z0.y); s3f[1] = H2(z1.x, z1.y);
            s3f[2] = H2(z0.z, z0.w); s3f[3] = H2(z1.z, z1.w);
            s3f[4] = H2(z2.x, z2.y); s3f[5] = H2(z3.x, z3.y);
            s3f[6] = H2(z2.z, z2.w); s3f[7] = H2(z3.z, z3.w);
            W1_MMA2(3, s3f[0], s3f[1], s3f[2], s3f[3], s3f[4], s3f[5], s3f[6], s3f[7]);
        }

        // node pair-0 loads (latency covered by phase-B edge steps)
        uint4 cc0 = __ldg((const uint4*)(nH + oH[0]));
        uint4 cc1 = __ldg((const uint4*)(nH + oH[1]));
        uint4 cc2 = __ldg((const uint4*)(nH + oH[2]));
        uint4 cc3 = __ldg((const uint4*)(nH + oH[3]));

        // pack e (+b_init) to fp16 — stays in registers (accE dies here)
        uint4 ehq[2][2][2];
        #pragma unroll
        for (int mt = 0; mt < 2; ++mt)
            #pragma unroll
            for (int hf = 0; hf < 2; ++hf) {
                const int h2 = hf * 2;
                #pragma unroll
                for (int j = 0; j < 2; ++j) {
                    const int J = 2 * j, J2 = 2 * j + 1;
                    float4 biA = *(const float4*)&sbi[J * 16 + t4 * 4];
                    float4 biB = *(const float4*)&sbi[J2 * 16 + t4 * 4];
                    uint4 U;
                    U.x = H2(accE[mt][2 * J][h2] + biA.x,      accE[mt][2 * J][h2 + 1] + biA.y);
                    U.y = H2(accE[mt][2 * J + 1][h2] + biA.z,  accE[mt][2 * J + 1][h2 + 1] + biA.w);
                    U.z = H2(accE[mt][2 * J2][h2] + biB.x,     accE[mt][2 * J2][h2 + 1] + biB.y);
                    U.w = H2(accE[mt][2 * J2 + 1][h2] + biB.z, accE[mt][2 * J2 + 1][h2 + 1] + biB.w);
                    ehq[mt][hf][j] = U;
                }
            }

        // ================ Phase B: big-GEMM (32 rows) ================
        float accB[2][9][4];
        #pragma unroll
        for (int h = 0; h < 2; ++h)
            #pragma unroll
            for (int b = 0; b < 9; ++b)
                #pragma unroll
                for (int c = 0; c < 4; ++c) accB[h][b][c] = 0.f;

        {
            float4 r0 = __ldg((const float4*)(eB + oE[0]));
            float4 r1 = __ldg((const float4*)(eB + oE[1]));
            float4 r2 = __ldg((const float4*)(eB + oE[2]));
            float4 r3 = __ldg((const float4*)(eB + oE[3]));
            float4 u0 = __ldg((const float4*)(eB + oE[0] + 64));
            float4 u1 = __ldg((const float4*)(eB + oE[1] + 64));
            float4 u2 = __ldg((const float4*)(eB + oE[2] + 64));
            float4 u3 = __ldg((const float4*)(eB + oE[3] + 64));
            { CVT8(r0, r1, r2, r3, a0, a1, b0, b1, a2, a3, b2, b3);
              WB_MMA2(0, a0, a1, b0, b1, a2, a3, b2, b3); }
            { CVT8(u0, u1, u2, u3, a0, a1, b0, b1, a2, a3, b2, b3);
              WB_MMA2(1, a0, a1, b0, b1, a2, a3, b2, b3); }
            WB_MMA2(2, s2f[0], s2f[1], s2f[2], s2f[3], s2f[4], s2f[5], s2f[6], s2f[7]);
            WB_MMA2(3, s3f[0], s3f[1], s3f[2], s3f[3], s3f[4], s3f[5], s3f[6], s3f[7]);
        }

        #pragma unroll
        for (int pj = 0; pj < 4; ++pj) {
            uint4 nn0, nn1, nn2, nn3;
            if (pj < 3) {
                const int np = pj + 1;
                const uint32_t* ob = (np >> 1) ? oT : oH;
                const uint32_t ofs = (uint32_t)((np & 1) * 64);
                nn0 = __ldg((const uint4*)(nH + ob[0] + ofs));
                nn1 = __ldg((const uint4*)(nH + ob[1] + ofs));
                nn2 = __ldg((const uint4*)(nH + ob[2] + ofs));
                nn3 = __ldg((const uint4*)(nH + ob[3] + ofs));
            }
            WB_MMA2(4 + 2 * pj, cc0.x, cc1.x, cc0.y, cc1.y, cc2.x, cc3.x, cc2.y, cc3.y);
            WB_MMA2(5 + 2 * pj, cc0.z, cc1.z, cc0.w, cc1.w, cc2.z, cc3.z, cc2.w, cc3.w);
            if (pj < 3) { cc0 = nn0; cc1 = nn1; cc2 = nn2; cc3 = nn3; }
        }

        // next-tile offsets (this tile's oE/oH/oT dead)
        SETOFFS(hidxN, tidxN, wtn);

        // ================ Epilogue ================
        #pragma unroll
        for (int mt = 0; mt < 2; ++mt) {
            #pragma unroll
            for (int hf = 0; hf < 2; ++hf) {
                const int h2  = hf * 2;
                const int row = mt * 16 + hf * 8 + gq;

                float p[16], s1 = 0.f, s2 = 0.f;
                #pragma unroll
                for (int J = 0; J < 4; ++J) {
                    float4 bm4 = *(const float4*)&sbm[J * 16 + t4 * 4];
                    float pre[4] = { accB[mt][2 * J][h2]     + bm4.x,
                                     accB[mt][2 * J][h2 + 1] + bm4.y,
                                     accB[mt][2 * J + 1][h2]     + bm4.z,
                                     accB[mt][2 * J + 1][h2 + 1] + bm4.w };
                    #pragma unroll
                    for (int c = 0; c < 4; ++c) {
                        float th = tanhap(pre[c]);
                        p[J * 4 + c] = th;
                        s1 += th; s2 += th * th;
                    }
                }
                s1 += __shfl_xor_sync(0xffffffffu, s1, 1);
                s1 += __shfl_xor_sync(0xffffffffu, s1, 2);
                s2 += __shfl_xor_sync(0xffffffffu, s2, 1);
                s2 += __shfl_xor_sync(0xffffffffu, s2, 2);
                float ap = accB[mt][8][h2] + bma;
                ap = __shfl_sync(0xffffffffu, ap, lane & ~3);
                const float alpha = __fdividef(1.f, 1.f + __expf(-ap));
                const float mean  = s1 * (1.f / 64.f);
                const float var   = s2 * (1.f / 64.f) - mean * mean;
                const float rstd  = rsqrtf(var + LN_EPS) * alpha;

                const uint4 q0 = ehq[mt][hf][0];
                const uint4 q1 = ehq[mt][hf][1];
                const uint32_t eharr[8] = { q0.x, q0.y, q0.z, q0.w, q1.x, q1.y, q1.z, q1.w };

                float y[16], u1 = 0.f, u2 = 0.f;
                #pragma unroll
                for (int J = 0; J < 4; ++J) {
                    float2 e01 = __half22float2(*(const __half2*)&eharr[J * 2]);
                    float2 e23 = __half22float2(*(const __half2*)&eharr[J * 2 + 1]);
                    float y0 = e01.x + (p[J * 4 + 0] - mean) * rstd;
                    float y1 = e01.y + (p[J * 4 + 1] - mean) * rstd;
                    float y2 = e23.x + (p[J * 4 + 2] - mean) * rstd;
                    float y3 = e23.y + (p[J * 4 + 3] - mean) * rstd;
                    y[J * 4 + 0] = y0; y[J * 4 + 1] = y1; y[J * 4 + 2] = y2; y[J * 4 + 3] = y3;
                    u1 += y0 + y1 + y2 + y3;
                    u2 += y0 * y0 + y1 * y1 + y2 * y2 + y3 * y3;
                }
                u1 += __shfl_xor_sync(0xffffffffu, u1, 1);
                u1 += __shfl_xor_sync(0xffffffffu, u1, 2);
                u2 += __shfl_xor_sync(0xffffffffu, u2, 1);
                u2 += __shfl_xor_sync(0xffffffffu, u2, 2);
                const float m2  = u1 * (1.f / 64.f);
                const float v2  = u2 * (1.f / 64.f) - m2 * m2;
                const float rs2 = rsqrtf(v2 + LN_EPS);

                if (row < rem) {
                    float* op = out + (size_t)(tb + row) * 64;
                    #pragma unroll
                    for (int J = 0; J < 4; ++J) {
                        float4 o;
                        o.x = (y[J * 4 + 0] - m2) * rs2;
                        o.y = (y[J * 4 + 1] - m2) * rs2;
                        o.z = (y[J * 4 + 2] - m2) * rs2;
                        o.w = (y[J * 4 + 3] - m2) * rs2;
                        __stcs((float4*)(op + J * 16 + t4 * 4), o);
                    }
                }
            }
            if (mt == 0) {
                // prefetch next tile's edge s0 across the second half-epilogue
                vc0 = __ldg((const float4*)(eB + oE[0]));
                vc1 = __ldg((const float4*)(eB + oE[1]));
                vc2 = __ldg((const float4*)(eB + oE[2]));
                vc3 = __ldg((const float4*)(eB + oE[3]));
            }
        }
    }
#undef LOADIDX
#undef SETOFFS
#undef WB_MMA2
#undef W1_MMA2
#undef CVT8
}

extern "C" void kernel_launch(void* const* d_in, const int* in_sizes, int n_in,
                              void* d_out, int out_size)
{
    const float* node_fts = (const float*)d_in[0];
    const float* edge_fts = (const float*)d_in[1];
    const void*  edges    = d_in[2];
    const float* W_init   = (const float*)d_in[3];
    const float* b_init   = (const float*)d_in[4];
    const float* W_mlp    = (const float*)d_in[5];
    const float* b_mlp    = (const float*)d_in[6];
    const float* W_alpha  = (const float*)d_in[7];
    const float* b_alpha  = (const float*)d_in[8];
    float*       out      = (float*)d_out;

    const int n_edges = in_sizes[1] / 64;
    const int n4      = in_sizes[0] / 4;
    const int ntiles  = (n_edges + 31) / 32;

    int nsm = 148;
    cudaDeviceGetAttribute(&nsm, cudaDevAttrMultiProcessorCount, 0);
    int need = (ntiles + 11) / 12;
    int grid = need < nsm ? need : nsm;

    const int prep_threads = n4 + 64 * 64 + 72 * 192 + 64 + 65;

    cudaFuncSetAttribute(edge_update_v17,
                         cudaFuncAttributeMaxDynamicSharedMemorySize, SMEM_BYTES);
    prep_all<<<(prep_threads + 255) / 256, 256>>>(node_fts, n4, W_init, b_init,
                                                  W_mlp, b_mlp, W_alpha, b_alpha,
                                                  (const long long*)edges);
    edge_update_v17<<<grid, NT, SMEM_BYTES>>>(edge_fts, edges, out, n_edges);
}